// round 16
// baseline (speedup 1.0000x reference)
#include <cuda_runtime.h>
#include <cstdint>

#define BDIM 128   // 16 element-groups × 8 threads; 4 elements/thread => 64 elems/CTA

// ---------------- packed-weight scratch (device globals; no allocation) ----------------
__device__ __align__(16) float g_W1[72 * 32];   // [j][i]: j<40 -> W_ih[i][j], else W_hh[i][j-40]
__device__ __align__(16) float g_F1[32 * 32];   // [j][i] = fc1_w[i][j]
__device__ __align__(16) float g_MW[32 * 32];   // [j][i] = mean_w[i][j]
__device__ __align__(16) float g_SW[32 * 32];   // [j][i] = std_w[i][j]
__device__ __align__(16) float g_b1[32];
__device__ __align__(16) float g_fb[32];
__device__ __align__(16) float g_mb[32];
__device__ __align__(16) float g_sb[32];

__global__ void pack_kernel(const float* __restrict__ W_ih, const float* __restrict__ W_hh,
                            const float* __restrict__ b_ih, const float* __restrict__ b_hh,
                            const float* __restrict__ fc1_w, const float* __restrict__ fc1_b,
                            const float* __restrict__ mean_w, const float* __restrict__ mean_b,
                            const float* __restrict__ std_w, const float* __restrict__ std_b) {
    int t = threadIdx.x;
    for (int idx = t; idx < 72 * 32; idx += blockDim.x) {
        int j = idx >> 5, i = idx & 31;
        g_W1[idx] = (j < 40) ? W_ih[i * 40 + j] : W_hh[i * 32 + (j - 40)];
    }
    for (int idx = t; idx < 32 * 32; idx += blockDim.x) {
        int j = idx >> 5, i = idx & 31;
        g_F1[idx] = fc1_w[i * 32 + j];
        g_MW[idx] = mean_w[i * 32 + j];
        g_SW[idx] = std_w[i * 32 + j];
    }
    if (t < 32) {
        g_b1[t] = b_ih[t] + b_hh[t];
        g_fb[t] = fc1_b[t];
        g_mb[t] = mean_b[t];
        g_sb[t] = std_b[t];
    }
}

// ---------------- f32x2 helpers: by-value / named-scalar only ----------------
__device__ __forceinline__ unsigned long long pk(float x) {
    unsigned long long r;
    asm("mov.b64 %0, {%1, %1};" : "=l"(r) : "f"(x));
    return r;
}
__device__ __forceinline__ float2 up(unsigned long long v) {
    float2 f;
    asm("mov.b64 {%0, %1}, %2;" : "=f"(f.x), "=f"(f.y) : "l"(v));
    return f;
}
#define FMA2(acc, w, x) asm("fma.rn.f32x2 %0, %1, %2, %0;" : "+l"(acc) : "l"(w), "l"(x))

// ---------------- activations ----------------
__device__ __forceinline__ float fast_tanh(float x) {
    x = fminf(fmaxf(x, -15.f), 15.f);
    float e = __expf(2.f * x);
    return __fdividef(e - 1.f, e + 1.f);
}
__device__ __forceinline__ float fast_elu(float x) {
    return x > 0.f ? x : (__expf(x) - 1.f);
}
__device__ __forceinline__ float softplus_eps(float x) {
    float ax = fabsf(x);
    return fmaxf(x, 0.f) + __logf(1.f + __expf(-ax)) + 1e-5f;
}

// one ulonglong2 weight load (=LDS.128) -> 8 f32x2 FMA (4 outputs x 4 elements)
#define STEP4(Wu, jIdx, fA, fB, fC, fD)                      \
    do {                                                     \
        ulonglong2 _w = (Wu)[(jIdx) * 8 + c];                \
        unsigned long long _x;                               \
        _x = pk(fA); FMA2(a0A, _w.x, _x); FMA2(a1A, _w.y, _x); \
        _x = pk(fB); FMA2(a0B, _w.x, _x); FMA2(a1B, _w.y, _x); \
        _x = pk(fC); FMA2(a0C, _w.x, _x); FMA2(a1C, _w.y, _x); \
        _x = pk(fD); FMA2(a0D, _w.x, _x); FMA2(a1D, _w.y, _x); \
    } while (0)

// read 4 x-values per element from smem (broadcast LDS.128) and do 4 STEP4s
#define BLOCK4(Wu, jb, SV)                                   \
    do {                                                     \
        float4 _xA = (SV)[eA * 8 + (jb)];                    \
        float4 _xB = (SV)[eB * 8 + (jb)];                    \
        float4 _xC = (SV)[eC * 8 + (jb)];                    \
        float4 _xD = (SV)[eD * 8 + (jb)];                    \
        STEP4(Wu, (jb) * 4 + 0, _xA.x, _xB.x, _xC.x, _xD.x); \
        STEP4(Wu, (jb) * 4 + 1, _xA.y, _xB.y, _xC.y, _xD.y); \
        STEP4(Wu, (jb) * 4 + 2, _xA.z, _xB.z, _xC.z, _xD.z); \
        STEP4(Wu, (jb) * 4 + 3, _xA.w, _xB.w, _xC.w, _xD.w); \
    } while (0)

// fused mean+std: 2 weight loads -> 16 f32x2 FMA
#define STEPMS(jIdx, fA, fB, fC, fD)                         \
    do {                                                     \
        ulonglong2 _m = MWu[(jIdx) * 8 + c];                 \
        ulonglong2 _q = SWu[(jIdx) * 8 + c];                 \
        unsigned long long _x;                               \
        _x = pk(fA); FMA2(m0A, _m.x, _x); FMA2(m1A, _m.y, _x); FMA2(q0A, _q.x, _x); FMA2(q1A, _q.y, _x); \
        _x = pk(fB); FMA2(m0B, _m.x, _x); FMA2(m1B, _m.y, _x); FMA2(q0B, _q.x, _x); FMA2(q1B, _q.y, _x); \
        _x = pk(fC); FMA2(m0C, _m.x, _x); FMA2(m1C, _m.y, _x); FMA2(q0C, _q.x, _x); FMA2(q1C, _q.y, _x); \
        _x = pk(fD); FMA2(m0D, _m.x, _x); FMA2(m1D, _m.y, _x); FMA2(q0D, _q.x, _x); FMA2(q1D, _q.y, _x); \
    } while (0)

#define BLOCKMS(jb)                                          \
    do {                                                     \
        float4 _xA = sHidv[eA * 8 + (jb)];                   \
        float4 _xB = sHidv[eB * 8 + (jb)];                   \
        float4 _xC = sHidv[eC * 8 + (jb)];                   \
        float4 _xD = sHidv[eD * 8 + (jb)];                   \
        STEPMS((jb) * 4 + 0, _xA.x, _xB.x, _xC.x, _xD.x);    \
        STEPMS((jb) * 4 + 1, _xA.y, _xB.y, _xC.y, _xD.y);    \
        STEPMS((jb) * 4 + 2, _xA.z, _xB.z, _xC.z, _xD.z);    \
        STEPMS((jb) * 4 + 3, _xA.w, _xB.w, _xC.w, _xD.w);    \
    } while (0)

// ---------------- main rollout kernel: 8 threads/elem x 4 elems/thread ----------------
__global__ __launch_bounds__(BDIM) void rssm_kernel(
    const float* __restrict__ s0, const float* __restrict__ h0,
    const float* __restrict__ actions, float* __restrict__ out,
    int B, int T, int nsteps)
{
    __shared__ __align__(16) float sW1[72 * 32];
    __shared__ __align__(16) float sF1[32 * 32];
    __shared__ __align__(16) float sMW[32 * 32];
    __shared__ __align__(16) float sSW[32 * 32];
    __shared__ __align__(16) float sb1[32];
    __shared__ __align__(16) float sfb[32];
    __shared__ __align__(16) float smb[32];
    __shared__ __align__(16) float ssb[32];
    __shared__ __align__(16) float sS[64 * 32];
    __shared__ __align__(16) float sH[64 * 32];
    __shared__ __align__(16) float sHid[64 * 32];

    {
        int t0 = threadIdx.x;
        for (int i = t0; i < 72 * 32; i += BDIM) sW1[i] = g_W1[i];
        for (int i = t0; i < 32 * 32; i += BDIM) {
            sF1[i] = g_F1[i];
            sMW[i] = g_MW[i];
            sSW[i] = g_SW[i];
        }
        if (t0 < 32) {
            sb1[t0] = g_b1[t0];
            sfb[t0] = g_fb[t0];
            smb[t0] = g_mb[t0];
            ssb[t0] = g_sb[t0];
        }
    }

    const int tid = threadIdx.x;
    const int c  = tid & 7;
    const int e  = tid >> 3;
    const int eA = e, eB = e + 16, eC = e + 32, eD = e + 48;
    const int bA = blockIdx.x * 64 + e;
    const int bB = bA + 16, bC = bA + 32, bD = bA + 48;

    float4* sSv   = (float4*)sS;
    float4* sHv   = (float4*)sH;
    float4* sHidv = (float4*)sHid;

    if (bD < B) {
        sSv[eA * 8 + c] = ((const float4*)(s0 + (size_t)bA * 32))[c];
        sHv[eA * 8 + c] = ((const float4*)(h0 + (size_t)bA * 32))[c];
        sSv[eB * 8 + c] = ((const float4*)(s0 + (size_t)bB * 32))[c];
        sHv[eB * 8 + c] = ((const float4*)(h0 + (size_t)bB * 32))[c];
        sSv[eC * 8 + c] = ((const float4*)(s0 + (size_t)bC * 32))[c];
        sHv[eC * 8 + c] = ((const float4*)(h0 + (size_t)bC * 32))[c];
        sSv[eD * 8 + c] = ((const float4*)(s0 + (size_t)bD * 32))[c];
        sHv[eD * 8 + c] = ((const float4*)(h0 + (size_t)bD * 32))[c];
    }
    __syncthreads();
    if (bD >= B) return;

    const ulonglong2* W1u = (const ulonglong2*)sW1;
    const ulonglong2* F1u = (const ulonglong2*)sF1;
    const ulonglong2* MWu = (const ulonglong2*)sMW;
    const ulonglong2* SWu = (const ulonglong2*)sSW;
    const ulonglong2 b1u = ((const ulonglong2*)sb1)[c];
    const ulonglong2 fbu = ((const ulonglong2*)sfb)[c];
    const ulonglong2 mbu = ((const ulonglong2*)smb)[c];
    const ulonglong2 sbu = ((const ulonglong2*)ssb)[c];

    const float4* actA = (const float4*)(actions + (size_t)bA * T * 8);
    const float4* actB = (const float4*)(actions + (size_t)bB * T * 8);
    const float4* actC = (const float4*)(actions + (size_t)bC * T * 8);
    const float4* actD = (const float4*)(actions + (size_t)bD * T * 8);
    float* outA = out + (size_t)bA * 64;
    float* outB = out + (size_t)bB * 64;
    float* outC = out + (size_t)bC * 64;
    float* outD = out + (size_t)bD * 64;

    // ---- action double-buffer: cur holds step t, prefetch t+1 at loop top ----
    float4 c0A = actA[0], c1A = actA[1];
    float4 c0B = actB[0], c1B = actB[1];
    float4 c0C = actC[0], c1C = actC[1];
    float4 c0D = actD[0], c1D = actD[1];

#pragma unroll 1
    for (int t = 0; t < nsteps; t++) {
        // prefetch next step's actions FIRST; latency hides under this step's FMAs
        int tn = (t + 1 < nsteps) ? (t + 1) : t;
        float4 n0A = actA[2 * tn], n1A = actA[2 * tn + 1];
        float4 n0B = actB[2 * tn], n1B = actB[2 * tn + 1];
        float4 n0C = actC[2 * tn], n1C = actC[2 * tn + 1];
        float4 n0D = actD[2 * tn], n1D = actD[2 * tn + 1];

        // ================= GEMM1: h_pre = W1 @ [s | a | h] + b1 =================
        unsigned long long a0A = b1u.x, a1A = b1u.y;
        unsigned long long a0B = b1u.x, a1B = b1u.y;
        unsigned long long a0C = b1u.x, a1C = b1u.y;
        unsigned long long a0D = b1u.x, a1D = b1u.y;
#pragma unroll
        for (int jb = 0; jb < 8; jb++) BLOCK4(W1u, jb, sSv);
        STEP4(W1u, 32, c0A.x, c0B.x, c0C.x, c0D.x);
        STEP4(W1u, 33, c0A.y, c0B.y, c0C.y, c0D.y);
        STEP4(W1u, 34, c0A.z, c0B.z, c0C.z, c0D.z);
        STEP4(W1u, 35, c0A.w, c0B.w, c0C.w, c0D.w);
        STEP4(W1u, 36, c1A.x, c1B.x, c1C.x, c1D.x);
        STEP4(W1u, 37, c1A.y, c1B.y, c1C.y, c1D.y);
        STEP4(W1u, 38, c1A.z, c1B.z, c1C.z, c1D.z);
        STEP4(W1u, 39, c1A.w, c1B.w, c1C.w, c1D.w);
#pragma unroll
        for (int jb = 0; jb < 8; jb++) BLOCK4(W1u + 40 * 8, jb, sHv);
        __syncwarp();
        {
            float2 vA0 = up(a0A), vA1 = up(a1A);
            float2 vB0 = up(a0B), vB1 = up(a1B);
            float2 vC0 = up(a0C), vC1 = up(a1C);
            float2 vD0 = up(a0D), vD1 = up(a1D);
            sHv[eA * 8 + c] = make_float4(fast_tanh(vA0.x), fast_tanh(vA0.y), fast_tanh(vA1.x), fast_tanh(vA1.y));
            sHv[eB * 8 + c] = make_float4(fast_tanh(vB0.x), fast_tanh(vB0.y), fast_tanh(vB1.x), fast_tanh(vB1.y));
            sHv[eC * 8 + c] = make_float4(fast_tanh(vC0.x), fast_tanh(vC0.y), fast_tanh(vC1.x), fast_tanh(vC1.y));
            sHv[eD * 8 + c] = make_float4(fast_tanh(vD0.x), fast_tanh(vD0.y), fast_tanh(vD1.x), fast_tanh(vD1.y));
        }
        __syncwarp();

        // rotate action buffers (consumed above; next step's data now current)
        c0A = n0A; c1A = n1A; c0B = n0B; c1B = n1B;
        c0C = n0C; c1C = n1C; c0D = n0D; c1D = n1D;

        // ================= GEMM2: hid = elu(F1 @ h + fb) =================
        a0A = fbu.x; a1A = fbu.y; a0B = fbu.x; a1B = fbu.y;
        a0C = fbu.x; a1C = fbu.y; a0D = fbu.x; a1D = fbu.y;
#pragma unroll
        for (int jb = 0; jb < 8; jb++) BLOCK4(F1u, jb, sHv);
        {
            float2 vA0 = up(a0A), vA1 = up(a1A);
            float2 vB0 = up(a0B), vB1 = up(a1B);
            float2 vC0 = up(a0C), vC1 = up(a1C);
            float2 vD0 = up(a0D), vD1 = up(a1D);
            sHidv[eA * 8 + c] = make_float4(fast_elu(vA0.x), fast_elu(vA0.y), fast_elu(vA1.x), fast_elu(vA1.y));
            sHidv[eB * 8 + c] = make_float4(fast_elu(vB0.x), fast_elu(vB0.y), fast_elu(vB1.x), fast_elu(vB1.y));
            sHidv[eC * 8 + c] = make_float4(fast_elu(vC0.x), fast_elu(vC0.y), fast_elu(vC1.x), fast_elu(vC1.y));
            sHidv[eD * 8 + c] = make_float4(fast_elu(vD0.x), fast_elu(vD0.y), fast_elu(vD1.x), fast_elu(vD1.y));
        }
        __syncwarp();

        // ================= GEMM3: fused mean+std =================
        unsigned long long m0A = mbu.x, m1A = mbu.y, q0A = sbu.x, q1A = sbu.y;
        unsigned long long m0B = mbu.x, m1B = mbu.y, q0B = sbu.x, q1B = sbu.y;
        unsigned long long m0C = mbu.x, m1C = mbu.y, q0C = sbu.x, q1C = sbu.y;
        unsigned long long m0D = mbu.x, m1D = mbu.y, q0D = sbu.x, q1D = sbu.y;
#pragma unroll
        for (int jb = 0; jb < 8; jb++) BLOCKMS(jb);

        // ---- epilogue: s <- mean; out[t][b] = [mean | softplus(std)+eps] ----
        {
            float4* o4A = (float4*)(outA + (size_t)t * B * 64);
            float4* o4B = (float4*)(outB + (size_t)t * B * 64);
            float4* o4C = (float4*)(outC + (size_t)t * B * 64);
            float4* o4D = (float4*)(outD + (size_t)t * B * 64);
            float2 u0, u1;
            u0 = up(m0A); u1 = up(m1A);
            { float4 mv = make_float4(u0.x, u0.y, u1.x, u1.y); o4A[c] = mv; sSv[eA * 8 + c] = mv; }
            u0 = up(m0B); u1 = up(m1B);
            { float4 mv = make_float4(u0.x, u0.y, u1.x, u1.y); o4B[c] = mv; sSv[eB * 8 + c] = mv; }
            u0 = up(m0C); u1 = up(m1C);
            { float4 mv = make_float4(u0.x, u0.y, u1.x, u1.y); o4C[c] = mv; sSv[eC * 8 + c] = mv; }
            u0 = up(m0D); u1 = up(m1D);
            { float4 mv = make_float4(u0.x, u0.y, u1.x, u1.y); o4D[c] = mv; sSv[eD * 8 + c] = mv; }
            u0 = up(q0A); u1 = up(q1A);
            o4A[8 + c] = make_float4(softplus_eps(u0.x), softplus_eps(u0.y), softplus_eps(u1.x), softplus_eps(u1.y));
            u0 = up(q0B); u1 = up(q1B);
            o4B[8 + c] = make_float4(softplus_eps(u0.x), softplus_eps(u0.y), softplus_eps(u1.x), softplus_eps(u1.y));
            u0 = up(q0C); u1 = up(q1C);
            o4C[8 + c] = make_float4(softplus_eps(u0.x), softplus_eps(u0.y), softplus_eps(u1.x), softplus_eps(u1.y));
            u0 = up(q0D); u1 = up(q1D);
            o4D[8 + c] = make_float4(softplus_eps(u0.x), softplus_eps(u0.y), softplus_eps(u1.x), softplus_eps(u1.y));
        }
        __syncwarp();
    }
}

// ---------------- entry point ----------------
extern "C" void kernel_launch(void* const* d_in, const int* in_sizes, int n_in,
                              void* d_out, int out_size) {
    const float* s0      = (const float*)d_in[0];
    const float* h0      = (const float*)d_in[1];
    const float* actions = (const float*)d_in[2];
    const float* W_ih    = (const float*)d_in[3];
    const float* W_hh    = (const float*)d_in[4];
    const float* b_ih    = (const float*)d_in[5];
    const float* b_hh    = (const float*)d_in[6];
    const float* fc1_w   = (const float*)d_in[7];
    const float* fc1_b   = (const float*)d_in[8];
    const float* mean_w  = (const float*)d_in[9];
    const float* mean_b  = (const float*)d_in[10];
    const float* std_w   = (const float*)d_in[11];
    const float* std_b   = (const float*)d_in[12];

    int B = in_sizes[0] / 32;                 // s0 is [B, 32]
    int T = in_sizes[2] / (B * 8);            // actions is [B, T, 8]
    int nsteps = out_size / (B * 64);         // out is [nsteps, B, 64]

    pack_kernel<<<1, 256>>>(W_ih, W_hh, b_ih, b_hh, fc1_w, fc1_b,
                            mean_w, mean_b, std_w, std_b);
    rssm_kernel<<<(B + 63) / 64, BDIM>>>(s0, h0, actions, (float*)d_out, B, T, nsteps);
}